// round 2
// baseline (speedup 1.0000x reference)
#include <cuda_runtime.h>
#include <cuda_bf16.h>
#include <math.h>

typedef unsigned long long ull;

#define BM 128
#define BN 128
#define BK 16
#define SPAD 132

#define NHEADS 16
#define LOG100F 4.6051701859880914f

// ---------------- scratch (device globals; allocation is forbidden) ----------
__device__ float g_q[512 * 16 * 64 * 64];   // [bw*16+h][n][d]
__device__ float g_k[512 * 16 * 64 * 64];
__device__ float g_v[512 * 16 * 64 * 64];
__device__ float g_o[32768 * 1024];         // attention output, window-row layout
__device__ float g_tab[225 * 16];           // CPB MLP output per (rel-pos, head)

// ---------------- packed fp32x2 helpers (SASS FFMA2) -------------------------
__device__ __forceinline__ ull ffma2(ull a, ull b, ull c) {
    ull d;
    asm("fma.rn.f32x2 %0, %1, %2, %3;" : "=l"(d) : "l"(a), "l"(b), "l"(c));
    return d;
}
__device__ __forceinline__ ull splat2(float x) {
    ull r;
    asm("mov.b64 %0, {%1, %1};" : "=l"(r) : "f"(x));
    return r;
}

// ---------------- CPB MLP: g_tab[225][16] ------------------------------------
__global__ void cpb_kernel(const float* __restrict__ w1, const float* __restrict__ b1,
                           const float* __restrict__ w2) {
    __shared__ float hid[512];
    int p = blockIdx.x;            // 0..224
    int j = threadIdx.x;           // 0..511
    float vh = (float)(p / 15 - 7) * (8.0f / 7.0f);
    float vw = (float)(p % 15 - 7) * (8.0f / 7.0f);
    float t0 = (vh > 0.f ? 1.f : (vh < 0.f ? -1.f : 0.f)) * log2f(fabsf(vh) + 1.0f) * (1.0f / 3.0f);
    float t1 = (vw > 0.f ? 1.f : (vw < 0.f ? -1.f : 0.f)) * log2f(fabsf(vw) + 1.0f) * (1.0f / 3.0f);
    float hv = t0 * w1[j * 2 + 0] + t1 * w1[j * 2 + 1] + b1[j];
    hid[j] = fmaxf(hv, 0.0f);
    __syncthreads();
    if (j < NHEADS) {
        const float* wr = w2 + j * 512;
        float s = 0.f;
        #pragma unroll 8
        for (int q = 0; q < 512; ++q) s += wr[q] * hid[q];
        g_tab[p * NHEADS + j] = s;
    }
}

// ---------------- GEMM building blocks ---------------------------------------
// row m of the shifted-window-partitioned x -> pointer into x
__device__ __forceinline__ const float* xrow_gather(const float* x, int m) {
    int bw = m >> 6, n = m & 63;
    int b = bw >> 2, wi = bw & 3;
    int hh = (((wi >> 1) << 3) + (n >> 3) + 4) & 15;   // xs[h'] = x[(h'+4)&15]
    int ww = (((wi & 1) << 3) + (n & 7) + 4) & 15;
    return x + (size_t)(((b << 4) + hh) * 16 + ww) * 1024;
}

__device__ __forceinline__ void stage_tiles(float* As, float* Bs,
        float4 a0, float4 a1, float4 b0, float4 b1, int tid) {
    int sm = tid >> 2;             // 0..63 (+64 for the second half)
    int sk = (tid & 3) * 4;
    float* pa = As + sk * SPAD + sm;
    pa[0 * SPAD] = a0.x; pa[1 * SPAD] = a0.y; pa[2 * SPAD] = a0.z; pa[3 * SPAD] = a0.w;
    pa += 64;
    pa[0 * SPAD] = a1.x; pa[1 * SPAD] = a1.y; pa[2 * SPAD] = a1.z; pa[3 * SPAD] = a1.w;
    float* pb = Bs + sk * SPAD + sm;
    pb[0 * SPAD] = b0.x; pb[1 * SPAD] = b0.y; pb[2 * SPAD] = b0.z; pb[3 * SPAD] = b0.w;
    pb += 64;
    pb[0 * SPAD] = b1.x; pb[1 * SPAD] = b1.y; pb[2 * SPAD] = b1.z; pb[3 * SPAD] = b1.w;
}

__device__ __forceinline__ void mm_block(const float* As, const float* Bs,
                                         int ty, int tx, ull acc[8][4]) {
    #pragma unroll
    for (int kk = 0; kk < BK; ++kk) {
        const float* ar = As + kk * SPAD + ty * 8;
        float4 A0 = *(const float4*)ar;
        float4 A1 = *(const float4*)(ar + 4);
        const ulonglong2* br = (const ulonglong2*)(Bs + kk * SPAD + tx * 8);
        ulonglong2 B0 = br[0];
        ulonglong2 B1 = br[1];
        float av[8] = {A0.x, A0.y, A0.z, A0.w, A1.x, A1.y, A1.z, A1.w};
        #pragma unroll
        for (int i = 0; i < 8; ++i) {
            ull a2 = splat2(av[i]);
            acc[i][0] = ffma2(a2, B0.x, acc[i][0]);
            acc[i][1] = ffma2(a2, B0.y, acc[i][1]);
            acc[i][2] = ffma2(a2, B1.x, acc[i][2]);
            acc[i][3] = ffma2(a2, B1.y, acc[i][3]);
        }
    }
}

// ---------------- QKV GEMM (fused shift/window gather) -----------------------
// grid = (24, 256): x = mat(3) * ntile(8), y = m-tile
__global__ __launch_bounds__(256)
void qkv_gemm(const float* __restrict__ x, const float* __restrict__ Wq,
              const float* __restrict__ Wk, const float* __restrict__ Wv,
              const float* __restrict__ bv) {
    __shared__ __align__(16) float As[2][BK * SPAD];
    __shared__ __align__(16) float Bs[2][BK * SPAD];
    int tid = threadIdx.x;
    int mat   = blockIdx.x >> 3;
    int jbase = (blockIdx.x & 7) * BN;
    const float* W = (mat == 0) ? Wq : (mat == 1) ? Wk : Wv;
    float* dstbuf  = (mat == 0) ? g_q : (mat == 1) ? g_k : g_v;

    int mbase = blockIdx.y * BM;
    int ko = (tid & 3) * 4;
    const float* rA0 = xrow_gather(x, mbase + (tid >> 2)) + ko;
    const float* rA1 = xrow_gather(x, mbase + (tid >> 2) + 64) + ko;
    const float* rB0 = W + (size_t)(jbase + (tid >> 2)) * 1024 + ko;
    const float* rB1 = rB0 + (size_t)64 * 1024;

    float4 a0 = *(const float4*)rA0;
    float4 a1 = *(const float4*)rA1;
    float4 b0 = *(const float4*)rB0;
    float4 b1 = *(const float4*)rB1;
    stage_tiles(As[0], Bs[0], a0, a1, b0, b1, tid);
    __syncthreads();

    ull acc[8][4];
    #pragma unroll
    for (int i = 0; i < 8; ++i)
        #pragma unroll
        for (int j = 0; j < 4; ++j) acc[i][j] = 0ull;

    int ty = tid >> 4, tx = tid & 15;
    int cur = 0;
    for (int kt = 0; kt < 63; ++kt) {
        int kb = (kt + 1) * BK;
        a0 = *(const float4*)(rA0 + kb);
        a1 = *(const float4*)(rA1 + kb);
        b0 = *(const float4*)(rB0 + kb);
        b1 = *(const float4*)(rB1 + kb);
        mm_block(As[cur], Bs[cur], ty, tx, acc);
        stage_tiles(As[cur ^ 1], Bs[cur ^ 1], a0, a1, b0, b1, tid);
        __syncthreads();
        cur ^= 1;
    }
    mm_block(As[cur], Bs[cur], ty, tx, acc);

    // scatter into head-major [bw][head][n][d]
    #pragma unroll
    for (int i = 0; i < 8; ++i) {
        int m = mbase + ty * 8 + i;
        int bw = m >> 6, n = m & 63;
        #pragma unroll
        for (int j = 0; j < 4; ++j) {
            float2 v = *(float2*)&acc[i][j];
            int jl = jbase + tx * 8 + j * 2;
            if (mat == 2) { v.x += bv[jl]; v.y += bv[jl + 1]; }
            int head = jl >> 6, dd = jl & 63;
            *(float2*)(dstbuf + ((size_t)(bw * 16 + head) * 64 + n) * 64 + dd) = v;
        }
    }
}

// ---------------- attention: one block per (window-instance, head) -----------
__device__ __forceinline__ int grp(int wi, int n) {
    int hs = ((wi >> 1) << 3) + (n >> 3);
    int ws = ((wi & 1) << 3) + (n & 7);
    int rg = hs < 8 ? 0 : (hs < 12 ? 1 : 2);
    int cg = ws < 8 ? 0 : (ws < 12 ? 1 : 2);
    return rg * 3 + cg;
}

__global__ __launch_bounds__(256)
void attn_kernel(const float* __restrict__ logit_scale) {
    __shared__ __align__(16) float qt[64 * 68];   // [k][i]; later reused for P (stride 65)
    __shared__ __align__(16) float kt[64 * 68];   // [k][j]; later reused for V [j][dd]
    __shared__ float nq[64], nk[64], sig[225];
    float* ps = qt;
    float* vs = kt;

    int tid = threadIdx.x;
    int bh = blockIdx.x;           // bw*16 + h
    int bw = bh >> 4;
    int h  = bh & 15;
    int wi = bw & 3;

    const float4* qg = (const float4*)(g_q + (size_t)bh * 4096);
    const float4* kg = (const float4*)(g_k + (size_t)bh * 4096);

    // load q,k transposed into smem: (n,dd) -> [dd][n]
    #pragma unroll
    for (int r = 0; r < 4; ++r) {
        int i = tid + 256 * r;
        int n = i >> 4, c = (i & 15) * 4;
        float4 v = qg[i];
        qt[(c + 0) * 68 + n] = v.x; qt[(c + 1) * 68 + n] = v.y;
        qt[(c + 2) * 68 + n] = v.z; qt[(c + 3) * 68 + n] = v.w;
        float4 w = kg[i];
        kt[(c + 0) * 68 + n] = w.x; kt[(c + 1) * 68 + n] = w.y;
        kt[(c + 2) * 68 + n] = w.z; kt[(c + 3) * 68 + n] = w.w;
    }
    if (tid < 225) sig[tid] = 16.0f / (1.0f + __expf(-g_tab[tid * NHEADS + h]));
    __syncthreads();

    // per-token norm factors (scale folded into q side)
    if (tid < 64) {
        float s = 0.f;
        #pragma unroll 8
        for (int k = 0; k < 64; ++k) { float v = qt[k * 68 + tid]; s += v * v; }
        float sc = __expf(fminf(logit_scale[h], LOG100F));
        nq[tid] = sc / fmaxf(sqrtf(s), 1e-12f);
    } else if (tid < 128) {
        int j = tid - 64;
        float s = 0.f;
        #pragma unroll 8
        for (int k = 0; k < 64; ++k) { float v = kt[k * 68 + j]; s += v * v; }
        nk[j] = 1.0f / fmaxf(sqrtf(s), 1e-12f);
    }
    __syncthreads();

    // S = q . k  (4x4 per thread)
    int ty = tid >> 4, tx = tid & 15;
    float acc[4][4];
    #pragma unroll
    for (int a = 0; a < 4; ++a)
        #pragma unroll
        for (int b = 0; b < 4; ++b) acc[a][b] = 0.f;
    #pragma unroll 4
    for (int k = 0; k < 64; ++k) {
        float4 qv = *(const float4*)(qt + k * 68 + ty * 4);
        float4 kv = *(const float4*)(kt + k * 68 + tx * 4);
        float qa[4] = {qv.x, qv.y, qv.z, qv.w};
        float ka[4] = {kv.x, kv.y, kv.z, kv.w};
        #pragma unroll
        for (int a = 0; a < 4; ++a)
            #pragma unroll
            for (int b = 0; b < 4; ++b) acc[a][b] += qa[a] * ka[b];
    }
    __syncthreads();   // all reads of qt/kt done

    // scale + bias + mask, write P-pre-softmax into ps; load V into vs
    #pragma unroll
    for (int a = 0; a < 4; ++a) {
        int i = ty * 4 + a;
        int gi = grp(wi, i);
        int ih = i >> 3, iw = i & 7;
        #pragma unroll
        for (int b = 0; b < 4; ++b) {
            int j = tx * 4 + b;
            float val;
            if (grp(wi, j) != gi) {
                val = -1e30f;
            } else {
                int p = (ih - (j >> 3) + 7) * 15 + (iw - (j & 7) + 7);
                val = acc[a][b] * nq[i] * nk[j] + sig[p];
            }
            ps[i * 65 + j] = val;
        }
    }
    {
        const float4* vg = (const float4*)(g_v + (size_t)bh * 4096);
        float4* vd = (float4*)vs;
        #pragma unroll
        for (int r = 0; r < 4; ++r) vd[tid + 256 * r] = vg[tid + 256 * r];
    }
    __syncthreads();

    // row softmax
    if (tid < 64) {
        float* row = ps + tid * 65;
        float mx = -1e30f;
        #pragma unroll 8
        for (int j = 0; j < 64; ++j) mx = fmaxf(mx, row[j]);
        float s = 0.f;
        #pragma unroll 8
        for (int j = 0; j < 64; ++j) { float e = __expf(row[j] - mx); row[j] = e; s += e; }
        float inv = 1.0f / s;
        #pragma unroll 8
        for (int j = 0; j < 64; ++j) row[j] *= inv;
    }
    __syncthreads();

    // O = P . V  (4x4 per thread), write to g_o window-row layout
    float oacc[4][4];
    #pragma unroll
    for (int a = 0; a < 4; ++a)
        #pragma unroll
        for (int b = 0; b < 4; ++b) oacc[a][b] = 0.f;
    #pragma unroll 4
    for (int j = 0; j < 64; ++j) {
        float4 vv = *(const float4*)(vs + j * 64 + tx * 4);
        float va[4] = {vv.x, vv.y, vv.z, vv.w};
        float pa[4];
        #pragma unroll
        for (int a = 0; a < 4; ++a) pa[a] = ps[(ty * 4 + a) * 65 + j];
        #pragma unroll
        for (int a = 0; a < 4; ++a)
            #pragma unroll
            for (int b = 0; b < 4; ++b) oacc[a][b] += pa[a] * va[b];
    }
    #pragma unroll
    for (int a = 0; a < 4; ++a) {
        int n = ty * 4 + a;
        float4 o4 = make_float4(oacc[a][0], oacc[a][1], oacc[a][2], oacc[a][3]);
        *(float4*)(g_o + ((size_t)bw * 64 + n) * 1024 + h * 64 + tx * 4) = o4;
    }
}

// ---------------- output GEMM (fused reverse shift/merge scatter) ------------
// grid = (8, 256)
__global__ __launch_bounds__(256)
void out_gemm(const float* __restrict__ Wo, const float* __restrict__ bo,
              float* __restrict__ out) {
    __shared__ __align__(16) float As[2][BK * SPAD];
    __shared__ __align__(16) float Bs[2][BK * SPAD];
    int tid = threadIdx.x;
    int jbase = blockIdx.x * BN;
    int mbase = blockIdx.y * BM;
    int ko = (tid & 3) * 4;
    const float* rA0 = g_o + (size_t)(mbase + (tid >> 2)) * 1024 + ko;
    const float* rA1 = rA0 + (size_t)64 * 1024;
    const float* rB0 = Wo + (size_t)(jbase + (tid >> 2)) * 1024 + ko;
    const float* rB1 = rB0 + (size_t)64 * 1024;

    float4 a0 = *(const float4*)rA0;
    float4 a1 = *(const float4*)rA1;
    float4 b0 = *(const float4*)rB0;
    float4 b1 = *(const float4*)rB1;
    stage_tiles(As[0], Bs[0], a0, a1, b0, b1, tid);
    __syncthreads();

    ull acc[8][4];
    #pragma unroll
    for (int i = 0; i < 8; ++i)
        #pragma unroll
        for (int j = 0; j < 4; ++j) acc[i][j] = 0ull;

    int ty = tid >> 4, tx = tid & 15;
    int cur = 0;
    for (int kt = 0; kt < 63; ++kt) {
        int kb = (kt + 1) * BK;
        a0 = *(const float4*)(rA0 + kb);
        a1 = *(const float4*)(rA1 + kb);
        b0 = *(const float4*)(rB0 + kb);
        b1 = *(const float4*)(rB1 + kb);
        mm_block(As[cur], Bs[cur], ty, tx, acc);
        stage_tiles(As[cur ^ 1], Bs[cur ^ 1], a0, a1, b0, b1, tid);
        __syncthreads();
        cur ^= 1;
    }
    mm_block(As[cur], Bs[cur], ty, tx, acc);

    // epilogue: +bo, reverse window partition + reverse cyclic shift
    #pragma unroll
    for (int i = 0; i < 8; ++i) {
        int m = mbase + ty * 8 + i;
        int bw = m >> 6, n = m & 63;
        int b = bw >> 2, wi = bw & 3;
        int hs = ((wi >> 1) << 3) + (n >> 3);
        int ws = ((wi & 1) << 3) + (n & 7);
        int hh = (hs + 4) & 15, ww = (ws + 4) & 15;
        float* orow = out + ((size_t)((b * 16 + hh) * 16 + ww)) * 1024;
        #pragma unroll
        for (int j = 0; j < 4; ++j) {
            float2 v = *(float2*)&acc[i][j];
            int jl = jbase + tx * 8 + j * 2;
            v.x += bo[jl]; v.y += bo[jl + 1];
            *(float2*)(orow + jl) = v;
        }
    }
}

// ---------------- launch ------------------------------------------------------
extern "C" void kernel_launch(void* const* d_in, const int* in_sizes, int n_in,
                              void* d_out, int out_size) {
    const float* x   = (const float*)d_in[0];
    const float* Wq  = (const float*)d_in[1];
    const float* Wk  = (const float*)d_in[2];
    const float* Wv  = (const float*)d_in[3];
    const float* bv  = (const float*)d_in[4];
    const float* Wo  = (const float*)d_in[5];
    const float* bo  = (const float*)d_in[6];
    const float* ls  = (const float*)d_in[7];
    const float* w1  = (const float*)d_in[8];
    const float* b1  = (const float*)d_in[9];
    const float* w2  = (const float*)d_in[10];
    float* out = (float*)d_out;

    cpb_kernel<<<225, 512>>>(w1, b1, w2);
    qkv_gemm<<<dim3(24, 256), 256>>>(x, Wq, Wk, Wv, bv);
    attn_kernel<<<8192, 256>>>(ls);
    out_gemm<<<dim3(8, 256), 256>>>(Wo, bo, out);
}

// round 4
// speedup vs baseline: 1.9794x; 1.9794x over previous
#include <cuda_runtime.h>
#include <cuda_bf16.h>
#include <math.h>

typedef unsigned long long ull;
typedef unsigned int uint;

#define NHEADS 16
#define LOG100F 4.6051701859880914f

// ---------------- scratch (device globals; allocation is forbidden) ----------
__device__ float g_q[512 * 16 * 64 * 64];                 // [bw*16+h][n][d] fp32
__device__ float g_k[512 * 16 * 64 * 64];
__device__ float g_v[512 * 16 * 64 * 64];
__device__ __nv_bfloat16 g_xc[32768 * 3072];              // A for QKV: [hi|hi|lo]
__device__ __nv_bfloat16 g_oc[32768 * 3072];              // A for OUT: [hi|hi|lo]
__device__ __nv_bfloat16 g_wc[4 * 1024 * 3072];           // B: [hi|lo|hi] per row
__device__ float g_tab[225 * 16];                         // CPB MLP table

// ---------------- CPB MLP: g_tab[225][16] ------------------------------------
__global__ void cpb_kernel(const float* __restrict__ w1, const float* __restrict__ b1,
                           const float* __restrict__ w2) {
    __shared__ float hid[512];
    int p = blockIdx.x;
    int j = threadIdx.x;
    float vh = (float)(p / 15 - 7) * (8.0f / 7.0f);
    float vw = (float)(p % 15 - 7) * (8.0f / 7.0f);
    float t0 = (vh > 0.f ? 1.f : (vh < 0.f ? -1.f : 0.f)) * log2f(fabsf(vh) + 1.0f) * (1.0f / 3.0f);
    float t1 = (vw > 0.f ? 1.f : (vw < 0.f ? -1.f : 0.f)) * log2f(fabsf(vw) + 1.0f) * (1.0f / 3.0f);
    float hv = t0 * w1[j * 2 + 0] + t1 * w1[j * 2 + 1] + b1[j];
    hid[j] = fmaxf(hv, 0.0f);
    __syncthreads();
    if (j < NHEADS) {
        const float* wr = w2 + j * 512;
        float s = 0.f;
        #pragma unroll 8
        for (int q = 0; q < 512; ++q) s += wr[q] * hid[q];
        g_tab[p * NHEADS + j] = s;
    }
}

// ---------------- conversion kernels ------------------------------------------
__device__ __forceinline__ const float* xrow_gather(const float* x, int m) {
    int bw = m >> 6, n = m & 63;
    int b = bw >> 2, wi = bw & 3;
    int hh = (((wi >> 1) << 3) + (n >> 3) + 4) & 15;
    int ww = (((wi & 1) << 3) + (n & 7) + 4) & 15;
    return x + (size_t)(((b << 4) + hh) * 16 + ww) * 1024;
}

__device__ __forceinline__ void split4(float4 v, __nv_bfloat162& h01, __nv_bfloat162& h23,
                                       __nv_bfloat162& l01, __nv_bfloat162& l23) {
    __nv_bfloat16 h0 = __float2bfloat16(v.x), h1 = __float2bfloat16(v.y);
    __nv_bfloat16 h2 = __float2bfloat16(v.z), h3 = __float2bfloat16(v.w);
    __nv_bfloat16 l0 = __float2bfloat16(v.x - __bfloat162float(h0));
    __nv_bfloat16 l1 = __float2bfloat16(v.y - __bfloat162float(h1));
    __nv_bfloat16 l2 = __float2bfloat16(v.z - __bfloat162float(h2));
    __nv_bfloat16 l3 = __float2bfloat16(v.w - __bfloat162float(h3));
    h01.x = h0; h01.y = h1; h23.x = h2; h23.y = h3;
    l01.x = l0; l01.y = l1; l23.x = l2; l23.y = l3;
}

// x -> g_xc with shifted-window gather; A layout [hi | hi | lo]
__global__ void conv_x(const float* __restrict__ x) {
    int m = blockIdx.x;
    int t = threadIdx.x;
    const float* src = xrow_gather(x, m);
    float4 v = ((const float4*)src)[t];
    __nv_bfloat162 h01, h23, l01, l23;
    split4(v, h01, h23, l01, l23);
    __nv_bfloat16* dst = g_xc + (size_t)m * 3072 + t * 4;
    *(__nv_bfloat162*)(dst)        = h01; *(__nv_bfloat162*)(dst + 2)    = h23;
    *(__nv_bfloat162*)(dst + 1024) = h01; *(__nv_bfloat162*)(dst + 1026) = h23;
    *(__nv_bfloat162*)(dst + 2048) = l01; *(__nv_bfloat162*)(dst + 2050) = l23;
}

// weights -> g_wc; B layout [hi | lo | hi]
__global__ void conv_w(const float* __restrict__ Wq, const float* __restrict__ Wk,
                       const float* __restrict__ Wv, const float* __restrict__ Wo) {
    int j = blockIdx.x;
    int mat = blockIdx.y;
    int t = threadIdx.x;
    const float* W = (mat == 0) ? Wq : (mat == 1) ? Wk : (mat == 2) ? Wv : Wo;
    float4 v = *(const float4*)(W + (size_t)j * 1024 + t * 4);
    __nv_bfloat162 h01, h23, l01, l23;
    split4(v, h01, h23, l01, l23);
    __nv_bfloat16* dst = g_wc + ((size_t)mat * 1024 + j) * 3072 + t * 4;
    *(__nv_bfloat162*)(dst)        = h01; *(__nv_bfloat162*)(dst + 2)    = h23;
    *(__nv_bfloat162*)(dst + 1024) = l01; *(__nv_bfloat162*)(dst + 1026) = l23;
    *(__nv_bfloat162*)(dst + 2048) = h01; *(__nv_bfloat162*)(dst + 2050) = h23;
}

// ---------------- mma.sync split-bf16 GEMM ------------------------------------
// CTA tile 128x128, K' = 3072 (96 chunks of 32), 8 warps (4 m x 2 n),
// warp tile 32x64, mma.m16n8k16, 4-stage cp.async pipeline.
// mode 0: QKV (scatter to g_q/g_k/g_v; bias=bv on mat 2)
// mode 1: OUT (reverse-shift scatter to outp; bias=bo)
#define STG_BYTES 20480      // per stage: A 128*80 + B 128*80
#define DYN_SMEM  (4 * STG_BYTES)

__device__ __forceinline__ void ldsm4(uint r[4], uint addr) {
    asm volatile("ldmatrix.sync.aligned.m8n8.x4.shared.b16 {%0,%1,%2,%3}, [%4];"
                 : "=r"(r[0]), "=r"(r[1]), "=r"(r[2]), "=r"(r[3]) : "r"(addr));
}
__device__ __forceinline__ void mma16816(float c[4], const uint a[4], uint b0, uint b1) {
    asm volatile(
        "mma.sync.aligned.m16n8k16.row.col.f32.bf16.bf16.f32 "
        "{%0,%1,%2,%3}, {%4,%5,%6,%7}, {%8,%9}, {%0,%1,%2,%3};"
        : "+f"(c[0]), "+f"(c[1]), "+f"(c[2]), "+f"(c[3])
        : "r"(a[0]), "r"(a[1]), "r"(a[2]), "r"(a[3]), "r"(b0), "r"(b1));
}

__global__ __launch_bounds__(256)
void mma_gemm(const __nv_bfloat16* __restrict__ Ag, const __nv_bfloat16* __restrict__ Bg,
              const float* __restrict__ bias, float* __restrict__ outp, int mode) {
    extern __shared__ char dynsm[];
    const int tid = threadIdx.x;
    const int wid = tid >> 5;
    const int lane = tid & 31;
    const int wm = wid >> 1;          // 0..3 -> m offset wm*32
    const int wn = wid & 1;           // 0..1 -> n offset wn*64
    const int jbase = blockIdx.x * 128;
    const int mbase = blockIdx.y * 128;

    uint smbase = (uint)__cvta_generic_to_shared(dynsm);

    // cp.async per-thread source rows / smem dst (4 x 16B per thread per chunk)
    const int r0 = tid >> 2, r1 = (tid + 256) >> 2;
    const int sg0 = (tid & 3) * 16, sg1 = ((tid + 256) & 3) * 16;
    const char* srcA0 = (const char*)(Ag + (size_t)(mbase + r0) * 3072) + sg0;
    const char* srcA1 = (const char*)(Ag + (size_t)(mbase + r1) * 3072) + sg1;
    const char* srcB0 = (const char*)(Bg + (size_t)(jbase + r0) * 3072) + sg0;
    const char* srcB1 = (const char*)(Bg + (size_t)(jbase + r1) * 3072) + sg1;
    const uint dA0 = smbase + r0 * 80 + sg0;
    const uint dA1 = smbase + r1 * 80 + sg1;
    const uint dB0 = smbase + 10240 + r0 * 80 + sg0;
    const uint dB1 = smbase + 10240 + r1 * 80 + sg1;

    auto load_chunk = [&](int c, int s) {
        uint so = s * STG_BYTES;
        long go = (long)c * 64;
        asm volatile("cp.async.cg.shared.global [%0], [%1], 16;" :: "r"(dA0 + so), "l"(srcA0 + go));
        asm volatile("cp.async.cg.shared.global [%0], [%1], 16;" :: "r"(dA1 + so), "l"(srcA1 + go));
        asm volatile("cp.async.cg.shared.global [%0], [%1], 16;" :: "r"(dB0 + so), "l"(srcB0 + go));
        asm volatile("cp.async.cg.shared.global [%0], [%1], 16;" :: "r"(dB1 + so), "l"(srcB1 + go));
    };

    // ldmatrix per-lane base offsets (row = lane&15, +16B for upper half lanes)
    const uint lmrow = (lane & 15) * 80 + (lane >> 4) * 16;
    const uint lmA = smbase + (wm * 32) * 80 + lmrow;            // + mt*1280 + ks*32
    const uint lmB = smbase + 10240 + (wn * 64) * 80 + lmrow;    // + p*1280  + ks*32

    float acc[2][8][4];
    #pragma unroll
    for (int i = 0; i < 2; ++i)
        #pragma unroll
        for (int j = 0; j < 8; ++j)
            #pragma unroll
            for (int q = 0; q < 4; ++q) acc[i][j][q] = 0.f;

    const int NCH = 96;
    #pragma unroll
    for (int s = 0; s < 3; ++s) {
        load_chunk(s, s);
        asm volatile("cp.async.commit_group;" ::: "memory");
    }

    for (int c = 0; c < NCH; ++c) {
        asm volatile("cp.async.wait_group 2;" ::: "memory");
        __syncthreads();
        if (c + 3 < NCH) load_chunk(c + 3, (c + 3) & 3);
        asm volatile("cp.async.commit_group;" ::: "memory");

        uint so = (c & 3) * STG_BYTES;
        #pragma unroll
        for (int ks = 0; ks < 2; ++ks) {
            uint a[2][4], b[4][4];
            #pragma unroll
            for (int mt = 0; mt < 2; ++mt)
                ldsm4(a[mt], lmA + so + mt * 1280 + ks * 32);
            #pragma unroll
            for (int p = 0; p < 4; ++p)
                ldsm4(b[p], lmB + so + p * 1280 + ks * 32);
            #pragma unroll
            for (int mt = 0; mt < 2; ++mt)
                #pragma unroll
                for (int nt = 0; nt < 8; ++nt) {
                    int p = nt >> 1;
                    uint b0 = (nt & 1) ? b[p][1] : b[p][0];
                    uint b1 = (nt & 1) ? b[p][3] : b[p][2];
                    mma16816(acc[mt][nt], a[mt], b0, b1);
                }
        }
    }

    // ---------------- epilogue: fused scatter ---------------------------------
    #pragma unroll
    for (int mt = 0; mt < 2; ++mt) {
        #pragma unroll
        for (int half = 0; half < 2; ++half) {
            int m = mbase + wm * 32 + mt * 16 + (lane >> 2) + half * 8;
            int bw = m >> 6, n = m & 63;
            if (mode == 0) {
                #pragma unroll
                for (int nt = 0; nt < 8; ++nt) {
                    int colg = jbase + wn * 64 + nt * 8 + (lane & 3) * 2;
                    int mat = colg >> 10;
                    int jl = colg & 1023;
                    int head = jl >> 6, dd = jl & 63;
                    float2 v;
                    v.x = acc[mt][nt][half * 2 + 0];
                    v.y = acc[mt][nt][half * 2 + 1];
                    if (mat == 2) { v.x += bias[jl]; v.y += bias[jl + 1]; }
                    float* dst = ((mat == 0) ? g_q : (mat == 1) ? g_k : g_v)
                               + ((size_t)(bw * 16 + head) * 64 + n) * 64 + dd;
                    *(float2*)dst = v;
                }
            } else {
                int b = bw >> 2, wi = bw & 3;
                int hs = ((wi >> 1) << 3) + (n >> 3);
                int ws = ((wi & 1) << 3) + (n & 7);
                int hh = (hs + 4) & 15, ww = (ws + 4) & 15;
                float* orow = outp + ((size_t)((b * 16 + hh) * 16 + ww)) * 1024;
                #pragma unroll
                for (int nt = 0; nt < 8; ++nt) {
                    int colg = jbase + wn * 64 + nt * 8 + (lane & 3) * 2;
                    float2 v;
                    v.x = acc[mt][nt][half * 2 + 0] + bias[colg];
                    v.y = acc[mt][nt][half * 2 + 1] + bias[colg + 1];
                    *(float2*)(orow + colg) = v;
                }
            }
        }
    }
}

// ---------------- attention: one block per (window-instance, head) -----------
__device__ __forceinline__ int grp(int wi, int n) {
    int hs = ((wi >> 1) << 3) + (n >> 3);
    int ws = ((wi & 1) << 3) + (n & 7);
    int rg = hs < 8 ? 0 : (hs < 12 ? 1 : 2);
    int cg = ws < 8 ? 0 : (ws < 12 ? 1 : 2);
    return rg * 3 + cg;
}

__global__ __launch_bounds__(256)
void attn_kernel(const float* __restrict__ logit_scale) {
    __shared__ __align__(16) float qt[64 * 68];
    __shared__ __align__(16) float kt[64 * 68];
    __shared__ float nq[64], nk[64], sig[225];
    float* ps = qt;
    float* vs = kt;

    int tid = threadIdx.x;
    int bh = blockIdx.x;
    int bw = bh >> 4;
    int hd = bh & 15;
    int wi = bw & 3;

    const float4* qg = (const float4*)(g_q + (size_t)bh * 4096);
    const float4* kg = (const float4*)(g_k + (size_t)bh * 4096);

    #pragma unroll
    for (int r = 0; r < 4; ++r) {
        int i = tid + 256 * r;
        int n = i >> 4, c = (i & 15) * 4;
        float4 v = qg[i];
        qt[(c + 0) * 68 + n] = v.x; qt[(c + 1) * 68 + n] = v.y;
        qt[(c + 2) * 68 + n] = v.z; qt[(c + 3) * 68 + n] = v.w;
        float4 w = kg[i];
        kt[(c + 0) * 68 + n] = w.x; kt[(c + 1) * 68 + n] = w.y;
        kt[(c + 2) * 68 + n] = w.z; kt[(c + 3) * 68 + n] = w.w;
    }
    if (tid < 225) sig[tid] = 16.0f / (1.0f + __expf(-g_tab[tid * NHEADS + hd]));
    __syncthreads();

    if (tid < 64) {
        float s = 0.f;
        #pragma unroll 8
        for (int k = 0; k < 64; ++k) { float v = qt[k * 68 + tid]; s += v * v; }
        float sc = __expf(fminf(logit_scale[hd], LOG100F));
        nq[tid] = sc / fmaxf(sqrtf(s), 1e-12f);
    } else if (tid < 128) {
        int j = tid - 64;
        float s = 0.f;
        #pragma unroll 8
        for (int k = 0; k < 64; ++k) { float v = kt[k * 68 + j]; s += v * v; }
        nk[j] = 1.0f / fmaxf(sqrtf(s), 1e-12f);
    }
    __syncthreads();

    int ty = tid >> 4, tx = tid & 15;
    float acc[4][4];
    #pragma unroll
    for (int a = 0; a < 4; ++a)
        #pragma unroll
        for (int b = 0; b < 4; ++b) acc[a][b] = 0.f;
    #pragma unroll 4
    for (int k = 0; k < 64; ++k) {
        float4 qv = *(const float4*)(qt + k * 68 + ty * 4);
        float4 kv = *(const float4*)(kt + k * 68 + tx * 4);
        float qa[4] = {qv.x, qv.y, qv.z, qv.w};
        float ka[4] = {kv.x, kv.y, kv.z, kv.w};
        #pragma unroll
        for (int a = 0; a < 4; ++a)
            #pragma unroll
            for (int b = 0; b < 4; ++b) acc[a][b] += qa[a] * ka[b];
    }
    __syncthreads();

    #pragma unroll
    for (int a = 0; a < 4; ++a) {
        int i = ty * 4 + a;
        int gi = grp(wi, i);
        int ih = i >> 3, iw = i & 7;
        #pragma unroll
        for (int b = 0; b < 4; ++b) {
            int j = tx * 4 + b;
            float val;
            if (grp(wi, j) != gi) {
                val = -1e30f;
            } else {
                int p = (ih - (j >> 3) + 7) * 15 + (iw - (j & 7) + 7);
                val = acc[a][b] * nq[i] * nk[j] + sig[p];
            }
            ps[i * 65 + j] = val;
        }
    }
    {
        const float4* vg = (const float4*)(g_v + (size_t)bh * 4096);
        float4* vd = (float4*)vs;
        #pragma unroll
        for (int r = 0; r < 4; ++r) vd[tid + 256 * r] = vg[tid + 256 * r];
    }
    __syncthreads();

    if (tid < 64) {
        float* row = ps + tid * 65;
        float mx = -1e30f;
        #pragma unroll 8
        for (int j = 0; j < 64; ++j) mx = fmaxf(mx, row[j]);
        float s = 0.f;
        #pragma unroll 8
        for (int j = 0; j < 64; ++j) { float e = __expf(row[j] - mx); row[j] = e; s += e; }
        float inv = 1.0f / s;
        #pragma unroll 8
        for (int j = 0; j < 64; ++j) row[j] *= inv;
    }
    __syncthreads();

    float oacc[4][4];
    #pragma unroll
    for (int a = 0; a < 4; ++a)
        #pragma unroll
        for (int b = 0; b < 4; ++b) oacc[a][b] = 0.f;
    #pragma unroll 4
    for (int j = 0; j < 64; ++j) {
        float4 vv = *(const float4*)(vs + j * 64 + tx * 4);
        float va[4] = {vv.x, vv.y, vv.z, vv.w};
        float pa[4];
        #pragma unroll
        for (int a = 0; a < 4; ++a) pa[a] = ps[(ty * 4 + a) * 65 + j];
        #pragma unroll
        for (int a = 0; a < 4; ++a)
            #pragma unroll
            for (int b = 0; b < 4; ++b) oacc[a][b] += pa[a] * va[b];
    }
    // write split-bf16 directly into g_oc (A layout [hi|hi|lo])
    #pragma unroll
    for (int a = 0; a < 4; ++a) {
        int n = ty * 4 + a;
        float4 v = make_float4(oacc[a][0], oacc[a][1], oacc[a][2], oacc[a][3]);
        __nv_bfloat162 h01, h23, l01, l23;
        split4(v, h01, h23, l01, l23);
        __nv_bfloat16* p = g_oc + (size_t)(bw * 64 + n) * 3072 + hd * 64 + tx * 4;
        *(__nv_bfloat162*)(p)        = h01; *(__nv_bfloat162*)(p + 2)    = h23;
        *(__nv_bfloat162*)(p + 1024) = h01; *(__nv_bfloat162*)(p + 1026) = h23;
        *(__nv_bfloat162*)(p + 2048) = l01; *(__nv_bfloat162*)(p + 2050) = l23;
    }
}

// ---------------- launch ------------------------------------------------------
extern "C" void kernel_launch(void* const* d_in, const int* in_sizes, int n_in,
                              void* d_out, int out_size) {
    const float* x   = (const float*)d_in[0];
    const float* Wq  = (const float*)d_in[1];
    const float* Wk  = (const float*)d_in[2];
    const float* Wv  = (const float*)d_in[3];
    const float* bv  = (const float*)d_in[4];
    const float* Wo  = (const float*)d_in[5];
    const float* bo  = (const float*)d_in[6];
    const float* ls  = (const float*)d_in[7];
    const float* w1  = (const float*)d_in[8];
    const float* b1  = (const float*)d_in[9];
    const float* w2  = (const float*)d_in[10];
    float* out = (float*)d_out;

    cudaFuncSetAttribute(mma_gemm, cudaFuncAttributeMaxDynamicSharedMemorySize, DYN_SMEM);

    cpb_kernel<<<225, 512>>>(w1, b1, w2);
    conv_w<<<dim3(1024, 4), 256>>>(Wq, Wk, Wv, Wo);
    conv_x<<<32768, 256>>>(x);

    __nv_bfloat16* xc = nullptr;
    __nv_bfloat16* oc = nullptr;
    __nv_bfloat16* wc = nullptr;
    cudaGetSymbolAddress((void**)&xc, g_xc);
    cudaGetSymbolAddress((void**)&oc, g_oc);
    cudaGetSymbolAddress((void**)&wc, g_wc);

    // QKV: A = g_xc [32768 x 3072], B = g_wc mats 0-2 (N = 3072)
    mma_gemm<<<dim3(24, 256), 256, DYN_SMEM>>>(xc, wc, bv, nullptr, 0);
    attn_kernel<<<8192, 256>>>(ls);
    // OUT: A = g_oc, B = g_wc mat 3 (N = 1024)
    mma_gemm<<<dim3(8, 256), 256, DYN_SMEM>>>(oc, wc + (size_t)3 * 1024 * 3072, bo, out, 1);
}

// round 5
// speedup vs baseline: 2.6153x; 1.3213x over previous
#include <cuda_runtime.h>
#include <cuda_bf16.h>
#include <math.h>

typedef unsigned long long ull;
typedef unsigned int uint;

#define NHEADS 16
#define LOG100F 4.6051701859880914f

// ---------------- scratch (device globals; allocation is forbidden) ----------
__device__ float g_q[512 * 16 * 64 * 64];                 // [bw*16+h][n][d] fp32
__device__ float g_k[512 * 16 * 64 * 64];
__device__ float g_v[512 * 16 * 64 * 64];
__device__ __nv_bfloat16 g_xc[32768 * 3072];              // A for QKV: [hi|hi|lo]
__device__ __nv_bfloat16 g_oc[32768 * 3072];              // A for OUT: [hi|hi|lo]
__device__ __nv_bfloat16 g_wc[4 * 1024 * 3072];           // B: [hi|lo|hi] per row
__device__ float g_tab[225 * 16];                         // CPB MLP table

// ---------------- packed fp32x2 helpers (SASS FFMA2) --------------------------
__device__ __forceinline__ ull ffma2(ull a, ull b, ull c) {
    ull d;
    asm("fma.rn.f32x2 %0, %1, %2, %3;" : "=l"(d) : "l"(a), "l"(b), "l"(c));
    return d;
}
__device__ __forceinline__ ull splat2(float x) {
    ull r;
    asm("mov.b64 %0, {%1, %1};" : "=l"(r) : "f"(x));
    return r;
}
__device__ __forceinline__ float2 unpk2(ull v) {
    float2 r;
    asm("mov.b64 {%0, %1}, %2;" : "=f"(r.x), "=f"(r.y) : "l"(v));
    return r;
}

// ---------------- CPB MLP: g_tab[225][16] ------------------------------------
__global__ void cpb_kernel(const float* __restrict__ w1, const float* __restrict__ b1,
                           const float* __restrict__ w2) {
    __shared__ float hid[512];
    int p = blockIdx.x;
    int j = threadIdx.x;
    float vh = (float)(p / 15 - 7) * (8.0f / 7.0f);
    float vw = (float)(p % 15 - 7) * (8.0f / 7.0f);
    float t0 = (vh > 0.f ? 1.f : (vh < 0.f ? -1.f : 0.f)) * log2f(fabsf(vh) + 1.0f) * (1.0f / 3.0f);
    float t1 = (vw > 0.f ? 1.f : (vw < 0.f ? -1.f : 0.f)) * log2f(fabsf(vw) + 1.0f) * (1.0f / 3.0f);
    float hv = t0 * w1[j * 2 + 0] + t1 * w1[j * 2 + 1] + b1[j];
    hid[j] = fmaxf(hv, 0.0f);
    __syncthreads();
    if (j < NHEADS) {
        const float* wr = w2 + j * 512;
        float s = 0.f;
        #pragma unroll 8
        for (int q = 0; q < 512; ++q) s += wr[q] * hid[q];
        g_tab[p * NHEADS + j] = s;
    }
}

// ---------------- conversion kernels ------------------------------------------
__device__ __forceinline__ const float* xrow_gather(const float* x, int m) {
    int bw = m >> 6, n = m & 63;
    int b = bw >> 2, wi = bw & 3;
    int hh = (((wi >> 1) << 3) + (n >> 3) + 4) & 15;
    int ww = (((wi & 1) << 3) + (n & 7) + 4) & 15;
    return x + (size_t)(((b << 4) + hh) * 16 + ww) * 1024;
}

__device__ __forceinline__ void split4(float4 v, __nv_bfloat162& h01, __nv_bfloat162& h23,
                                       __nv_bfloat162& l01, __nv_bfloat162& l23) {
    __nv_bfloat16 h0 = __float2bfloat16(v.x), h1 = __float2bfloat16(v.y);
    __nv_bfloat16 h2 = __float2bfloat16(v.z), h3 = __float2bfloat16(v.w);
    __nv_bfloat16 l0 = __float2bfloat16(v.x - __bfloat162float(h0));
    __nv_bfloat16 l1 = __float2bfloat16(v.y - __bfloat162float(h1));
    __nv_bfloat16 l2 = __float2bfloat16(v.z - __bfloat162float(h2));
    __nv_bfloat16 l3 = __float2bfloat16(v.w - __bfloat162float(h3));
    h01.x = h0; h01.y = h1; h23.x = h2; h23.y = h3;
    l01.x = l0; l01.y = l1; l23.x = l2; l23.y = l3;
}

// x -> g_xc with shifted-window gather; A layout [hi | hi | lo]
__global__ void conv_x(const float* __restrict__ x) {
    int m = blockIdx.x;
    int t = threadIdx.x;
    const float* src = xrow_gather(x, m);
    float4 v = ((const float4*)src)[t];
    __nv_bfloat162 h01, h23, l01, l23;
    split4(v, h01, h23, l01, l23);
    __nv_bfloat16* dst = g_xc + (size_t)m * 3072 + t * 4;
    *(__nv_bfloat162*)(dst)        = h01; *(__nv_bfloat162*)(dst + 2)    = h23;
    *(__nv_bfloat162*)(dst + 1024) = h01; *(__nv_bfloat162*)(dst + 1026) = h23;
    *(__nv_bfloat162*)(dst + 2048) = l01; *(__nv_bfloat162*)(dst + 2050) = l23;
}

// weights -> g_wc; B layout [hi | lo | hi]
__global__ void conv_w(const float* __restrict__ Wq, const float* __restrict__ Wk,
                       const float* __restrict__ Wv, const float* __restrict__ Wo) {
    int j = blockIdx.x;
    int mat = blockIdx.y;
    int t = threadIdx.x;
    const float* W = (mat == 0) ? Wq : (mat == 1) ? Wk : (mat == 2) ? Wv : Wo;
    float4 v = *(const float4*)(W + (size_t)j * 1024 + t * 4);
    __nv_bfloat162 h01, h23, l01, l23;
    split4(v, h01, h23, l01, l23);
    __nv_bfloat16* dst = g_wc + ((size_t)mat * 1024 + j) * 3072 + t * 4;
    *(__nv_bfloat162*)(dst)        = h01; *(__nv_bfloat162*)(dst + 2)    = h23;
    *(__nv_bfloat162*)(dst + 1024) = l01; *(__nv_bfloat162*)(dst + 1026) = l23;
    *(__nv_bfloat162*)(dst + 2048) = h01; *(__nv_bfloat162*)(dst + 2050) = h23;
}

// ---------------- mma.sync split-bf16 GEMM ------------------------------------
// CTA tile 128x128, K' = 3072 -> 48 chunks of 64, 8 warps (4m x 2n),
// warp tile 32x64, mma.m16n8k16, 3-stage cp.async pipeline, XOR-swizzled smem.
#define NCH 48
#define STG 32768            // per stage: A 128*128B + B 128*128B
#define DYN_SMEM (3 * STG)   // 98304

__device__ __forceinline__ void ldsm4(uint r[4], uint addr) {
    asm volatile("ldmatrix.sync.aligned.m8n8.x4.shared.b16 {%0,%1,%2,%3}, [%4];"
                 : "=r"(r[0]), "=r"(r[1]), "=r"(r[2]), "=r"(r[3]) : "r"(addr));
}
__device__ __forceinline__ void mma16816(float c[4], const uint a[4], uint b0, uint b1) {
    asm volatile(
        "mma.sync.aligned.m16n8k16.row.col.f32.bf16.bf16.f32 "
        "{%0,%1,%2,%3}, {%4,%5,%6,%7}, {%8,%9}, {%0,%1,%2,%3};"
        : "+f"(c[0]), "+f"(c[1]), "+f"(c[2]), "+f"(c[3])
        : "r"(a[0]), "r"(a[1]), "r"(a[2]), "r"(a[3]), "r"(b0), "r"(b1));
}

__global__ __launch_bounds__(256, 2)
void mma_gemm(const __nv_bfloat16* __restrict__ Ag, const __nv_bfloat16* __restrict__ Bg,
              const float* __restrict__ bias, float* __restrict__ outp, int mode) {
    extern __shared__ char dynsm[];
    const int tid = threadIdx.x;
    const int wid = tid >> 5;
    const int lane = tid & 31;
    const int wm = wid >> 1;
    const int wn = wid & 1;
    const int jbase = blockIdx.x * 128;
    const int mbase = blockIdx.y * 128;

    uint smbase = (uint)__cvta_generic_to_shared(dynsm);

    // static per-thread cp.async mapping: 4 units A + 4 units B per chunk
    uint aoff[4], boff[4];
    const char* asrc[4];
    const char* bsrc[4];
    #pragma unroll
    for (int i = 0; i < 4; ++i) {
        int u = tid + 256 * i;
        int row = u >> 3, slot = u & 7;
        uint off = row * 128 + ((slot * 16) ^ ((row & 7) << 4));
        aoff[i] = off;
        boff[i] = 16384 + off;
        asrc[i] = (const char*)(Ag + (size_t)(mbase + row) * 3072 + slot * 8);
        bsrc[i] = (const char*)(Bg + (size_t)(jbase + row) * 3072 + slot * 8);
    }

    auto load_chunk = [&](int c, int s) {
        uint so = smbase + s * STG;
        long gc = (long)c * 128;
        #pragma unroll
        for (int i = 0; i < 4; ++i) {
            asm volatile("cp.async.cg.shared.global [%0], [%1], 16;"
                         :: "r"(so + aoff[i]), "l"(asrc[i] + gc));
            asm volatile("cp.async.cg.shared.global [%0], [%1], 16;"
                         :: "r"(so + boff[i]), "l"(bsrc[i] + gc));
        }
    };

    // ldsm address pieces: addr = stage + rbase + (kx ^ xorv)
    const uint xorv = (lane & 7) << 4;
    const uint hi16 = (lane >> 4) * 16;
    uint rbA[2], rbB[4];
    #pragma unroll
    for (int mt = 0; mt < 2; ++mt)
        rbA[mt] = (wm * 32 + mt * 16 + (lane & 15)) * 128;
    #pragma unroll
    for (int p = 0; p < 4; ++p)
        rbB[p] = 16384 + (wn * 64 + p * 16 + (lane & 15)) * 128;
    uint kx[4];
    #pragma unroll
    for (int ks = 0; ks < 4; ++ks) kx[ks] = (ks * 32 + hi16) ^ xorv;

    float acc[2][8][4];
    #pragma unroll
    for (int i = 0; i < 2; ++i)
        #pragma unroll
        for (int j = 0; j < 8; ++j)
            #pragma unroll
            for (int q = 0; q < 4; ++q) acc[i][j][q] = 0.f;

    load_chunk(0, 0);
    asm volatile("cp.async.commit_group;" ::: "memory");
    load_chunk(1, 1);
    asm volatile("cp.async.commit_group;" ::: "memory");

    int slot2 = 2;   // slot for chunk c+2
    for (int c = 0; c < NCH; ++c) {
        if (c + 2 < NCH) load_chunk(c + 2, slot2);
        asm volatile("cp.async.commit_group;" ::: "memory");
        asm volatile("cp.async.wait_group 2;" ::: "memory");
        __syncthreads();

        uint so = smbase + (slot2 == 2 ? 0u : (slot2 == 0 ? 1u : 2u)) * STG; // slot of chunk c = (c)%3
        // (c%3): c, slot2=(c+2)%3 -> c%3 = (slot2+1)%3
        so = smbase + (uint)((slot2 + 1) % 3) * STG;

        #pragma unroll
        for (int ks = 0; ks < 4; ++ks) {
            uint a[2][4], b[4][4];
            #pragma unroll
            for (int mt = 0; mt < 2; ++mt)
                ldsm4(a[mt], so + rbA[mt] + kx[ks]);
            #pragma unroll
            for (int p = 0; p < 4; ++p)
                ldsm4(b[p], so + rbB[p] + kx[ks]);
            #pragma unroll
            for (int mt = 0; mt < 2; ++mt)
                #pragma unroll
                for (int nt = 0; nt < 8; ++nt) {
                    int p = nt >> 1;
                    uint b0 = (nt & 1) ? b[p][1] : b[p][0];
                    uint b1 = (nt & 1) ? b[p][3] : b[p][2];
                    mma16816(acc[mt][nt], a[mt], b0, b1);
                }
        }
        __syncthreads();   // reads of slot c%3 done before next iter overwrites it
        slot2 = (slot2 + 1) % 3;
    }

    // ---------------- epilogue: fused scatter ---------------------------------
    #pragma unroll
    for (int mt = 0; mt < 2; ++mt) {
        #pragma unroll
        for (int half = 0; half < 2; ++half) {
            int m = mbase + wm * 32 + mt * 16 + (lane >> 2) + half * 8;
            int bw = m >> 6, n = m & 63;
            if (mode == 0) {
                #pragma unroll
                for (int nt = 0; nt < 8; ++nt) {
                    int colg = jbase + wn * 64 + nt * 8 + (lane & 3) * 2;
                    int mat = colg >> 10;
                    int jl = colg & 1023;
                    int head = jl >> 6, dd = jl & 63;
                    float2 v;
                    v.x = acc[mt][nt][half * 2 + 0];
                    v.y = acc[mt][nt][half * 2 + 1];
                    if (mat == 2) { v.x += bias[jl]; v.y += bias[jl + 1]; }
                    float* dst = ((mat == 0) ? g_q : (mat == 1) ? g_k : g_v)
                               + ((size_t)(bw * 16 + head) * 64 + n) * 64 + dd;
                    *(float2*)dst = v;
                }
            } else {
                int b = bw >> 2, wi = bw & 3;
                int hs = ((wi >> 1) << 3) + (n >> 3);
                int ws = ((wi & 1) << 3) + (n & 7);
                int hh = (hs + 4) & 15, ww = (ws + 4) & 15;
                float* orow = outp + ((size_t)((b * 16 + hh) * 16 + ww)) * 1024;
                #pragma unroll
                for (int nt = 0; nt < 8; ++nt) {
                    int colg = jbase + wn * 64 + nt * 8 + (lane & 3) * 2;
                    float2 v;
                    v.x = acc[mt][nt][half * 2 + 0] + bias[colg];
                    v.y = acc[mt][nt][half * 2 + 1] + bias[colg + 1];
                    *(float2*)(orow + colg) = v;
                }
            }
        }
    }
}

// ---------------- attention: one block per (window-instance, head) -----------
__device__ __forceinline__ int grp(int wi, int n) {
    int hs = ((wi >> 1) << 3) + (n >> 3);
    int ws = ((wi & 1) << 3) + (n & 7);
    int rg = hs < 8 ? 0 : (hs < 12 ? 1 : 2);
    int cg = ws < 8 ? 0 : (ws < 12 ? 1 : 2);
    return rg * 3 + cg;
}

__global__ __launch_bounds__(256)
void attn_kernel(const float* __restrict__ logit_scale) {
    __shared__ __align__(16) float qt[64 * 68];   // [d][n]; later reused for P (stride 65)
    __shared__ __align__(16) float kt[64 * 68];   // [d][n]; later reused for V [n][d]
    __shared__ float nq[64], nk[64], sig[225];
    float* ps = qt;
    float* vs = kt;

    int tid = threadIdx.x;
    int bh = blockIdx.x;
    int bw = bh >> 4;
    int hd = bh & 15;
    int wi = bw & 3;

    const float4* qg = (const float4*)(g_q + (size_t)bh * 4096);
    const float4* kg = (const float4*)(g_k + (size_t)bh * 4096);

    #pragma unroll
    for (int r = 0; r < 4; ++r) {
        int i = tid + 256 * r;
        int n = i >> 4, c = (i & 15) * 4;
        float4 v = qg[i];
        qt[(c + 0) * 68 + n] = v.x; qt[(c + 1) * 68 + n] = v.y;
        qt[(c + 2) * 68 + n] = v.z; qt[(c + 3) * 68 + n] = v.w;
        float4 w = kg[i];
        kt[(c + 0) * 68 + n] = w.x; kt[(c + 1) * 68 + n] = w.y;
        kt[(c + 2) * 68 + n] = w.z; kt[(c + 3) * 68 + n] = w.w;
    }
    if (tid < 225) sig[tid] = 16.0f / (1.0f + __expf(-g_tab[tid * NHEADS + hd]));
    __syncthreads();

    // per-token norm factors: 2 lanes per row, all 256 threads busy
    {
        int half = tid & 1;
        int row = (tid >> 1) & 63;
        const float* base = (tid < 128) ? qt : kt;
        float s = 0.f;
        int k0 = half * 32;
        #pragma unroll 8
        for (int k = k0; k < k0 + 32; ++k) { float v = base[k * 68 + row]; s += v * v; }
        s += __shfl_xor_sync(0xFFFFFFFFu, s, 1);
        if (!half) {
            float rr = fmaxf(sqrtf(s), 1e-12f);
            if (tid < 128) nq[row] = __expf(fminf(logit_scale[hd], LOG100F)) / rr;
            else           nk[row] = 1.0f / rr;
        }
    }
    __syncthreads();

    // S = q . k  (4x4 per thread, packed f32x2)
    int ty = tid >> 4, tx = tid & 15;
    ull acc2[4][2];
    #pragma unroll
    for (int a = 0; a < 4; ++a) { acc2[a][0] = 0ull; acc2[a][1] = 0ull; }
    #pragma unroll 4
    for (int k = 0; k < 64; ++k) {
        float4 qv = *(const float4*)(qt + k * 68 + ty * 4);
        ulonglong2 kv = *(const ulonglong2*)(kt + k * 68 + tx * 4);
        float qa[4] = {qv.x, qv.y, qv.z, qv.w};
        #pragma unroll
        for (int a = 0; a < 4; ++a) {
            ull a2 = splat2(qa[a]);
            acc2[a][0] = ffma2(a2, kv.x, acc2[a][0]);
            acc2[a][1] = ffma2(a2, kv.y, acc2[a][1]);
        }
    }
    __syncthreads();

    // scale + bias + mask -> ps; load V -> vs
    #pragma unroll
    for (int a = 0; a < 4; ++a) {
        int i = ty * 4 + a;
        int gi = grp(wi, i);
        int ih = i >> 3, iw = i & 7;
        float2 pr[2] = { unpk2(acc2[a][0]), unpk2(acc2[a][1]) };
        #pragma unroll
        for (int b = 0; b < 4; ++b) {
            int j = tx * 4 + b;
            float sv = (b & 1) ? pr[b >> 1].y : pr[b >> 1].x;
            float val;
            if (grp(wi, j) != gi) {
                val = -1e30f;
            } else {
                int p = (ih - (j >> 3) + 7) * 15 + (iw - (j & 7) + 7);
                val = sv * nq[i] * nk[j] + sig[p];
            }
            ps[i * 65 + j] = val;
        }
    }
    {
        const float4* vg = (const float4*)(g_v + (size_t)bh * 4096);
        float4* vd = (float4*)vs;
        #pragma unroll
        for (int r = 0; r < 4; ++r) vd[tid + 256 * r] = vg[tid + 256 * r];
    }
    __syncthreads();

    // row softmax, 4 threads per row
    {
        int r = tid >> 2, q4 = tid & 3;
        float* row = ps + r * 65 + q4 * 16;
        float mx = -1e30f;
        #pragma unroll
        for (int j = 0; j < 16; ++j) mx = fmaxf(mx, row[j]);
        mx = fmaxf(mx, __shfl_xor_sync(0xFFFFFFFFu, mx, 1));
        mx = fmaxf(mx, __shfl_xor_sync(0xFFFFFFFFu, mx, 2));
        float s = 0.f;
        #pragma unroll
        for (int j = 0; j < 16; ++j) { float e = __expf(row[j] - mx); row[j] = e; s += e; }
        s += __shfl_xor_sync(0xFFFFFFFFu, s, 1);
        s += __shfl_xor_sync(0xFFFFFFFFu, s, 2);
        float inv = 1.0f / s;
        #pragma unroll
        for (int j = 0; j < 16; ++j) row[j] *= inv;
    }
    __syncthreads();

    // O = P . V  (packed f32x2)
    ull o2[4][2];
    #pragma unroll
    for (int a = 0; a < 4; ++a) { o2[a][0] = 0ull; o2[a][1] = 0ull; }
    #pragma unroll 4
    for (int j = 0; j < 64; ++j) {
        ulonglong2 vv = *(const ulonglong2*)(vs + j * 64 + tx * 4);
        #pragma unroll
        for (int a = 0; a < 4; ++a) {
            ull a2 = splat2(ps[(ty * 4 + a) * 65 + j]);
            o2[a][0] = ffma2(a2, vv.x, o2[a][0]);
            o2[a][1] = ffma2(a2, vv.y, o2[a][1]);
        }
    }
    // write split-bf16 directly into g_oc (A layout [hi|hi|lo])
    #pragma unroll
    for (int a = 0; a < 4; ++a) {
        int n = ty * 4 + a;
        float2 p0 = unpk2(o2[a][0]), p1 = unpk2(o2[a][1]);
        float4 v = make_float4(p0.x, p0.y, p1.x, p1.y);
        __nv_bfloat162 h01, h23, l01, l23;
        split4(v, h01, h23, l01, l23);
        __nv_bfloat16* p = g_oc + (size_t)(bw * 64 + n) * 3072 + hd * 64 + tx * 4;
        *(__nv_bfloat162*)(p)        = h01; *(__nv_bfloat162*)(p + 2)    = h23;
        *(__nv_bfloat162*)(p + 1024) = h01; *(__nv_bfloat162*)(p + 1026) = h23;
        *(__nv_bfloat162*)(p + 2048) = l01; *(__nv_bfloat162*)(p + 2050) = l23;
    }
}

// ---------------- launch ------------------------------------------------------
extern "C" void kernel_launch(void* const* d_in, const int* in_sizes, int n_in,
                              void* d_out, int out_size) {
    const float* x   = (const float*)d_in[0];
    const float* Wq  = (const float*)d_in[1];
    const float* Wk  = (const float*)d_in[2];
    const float* Wv  = (const float*)d_in[3];
    const float* bv  = (const float*)d_in[4];
    const float* Wo  = (const float*)d_in[5];
    const float* bo  = (const float*)d_in[6];
    const float* ls  = (const float*)d_in[7];
    const float* w1  = (const float*)d_in[8];
    const float* b1  = (const float*)d_in[9];
    const float* w2  = (const float*)d_in[10];
    float* out = (float*)d_out;

    cudaFuncSetAttribute(mma_gemm, cudaFuncAttributeMaxDynamicSharedMemorySize, DYN_SMEM);

    cpb_kernel<<<225, 512>>>(w1, b1, w2);
    conv_w<<<dim3(1024, 4), 256>>>(Wq, Wk, Wv, Wo);
    conv_x<<<32768, 256>>>(x);

    __nv_bfloat16* xc = nullptr;
    __nv_bfloat16* oc = nullptr;
    __nv_bfloat16* wc = nullptr;
    cudaGetSymbolAddress((void**)&xc, g_xc);
    cudaGetSymbolAddress((void**)&oc, g_oc);
    cudaGetSymbolAddress((void**)&wc, g_wc);

    // QKV: A = g_xc [32768 x 3072], B = g_wc mats 0-2 (N = 3072)
    mma_gemm<<<dim3(24, 256), 256, DYN_SMEM>>>(xc, wc, bv, nullptr, 0);
    attn_kernel<<<8192, 256>>>(ls);
    // OUT: A = g_oc, B = g_wc mat 3 (N = 1024)
    mma_gemm<<<dim3(8, 256), 256, DYN_SMEM>>>(oc, wc + (size_t)3 * 1024 * 3072, bo, out, 1);
}